// round 13
// baseline (speedup 1.0000x reference)
#include <cuda_runtime.h>
#include <cstdint>

#define C_   16
#define H_   64
#define W_   64
#define KL_  25
#define O_   32
#define HW_  4096

// Fragment-ordered idx: uint4 e = (((c*64+trow)*4+mg)*2+sg)*32 + lane ; 8 u16
// byte offsets (word*4) into the channel window; word in [0,320], 320 = zero
// sentinel. 4 MB.
__device__ __align__(16) unsigned short g_idxf[16 * 64 * 4 * 2 * 32 * 8];
// Pre-built fp16x2 B fragments: [c][s][hp][lane][4 u32] = 32 KB (read via L1 LDG)
__device__ __align__(16) uint32_t g_bfrag16[8192];

__device__ __forceinline__ uint32_t smem_u32(const void* p) {
    uint32_t a;
    asm("{ .reg .u64 t; cvta.to.shared.u64 t, %1; cvt.u32.u64 %0, t; }" : "=r"(a) : "l"(p));
    return a;
}
__device__ __forceinline__ uint32_t f16x2_pack(float lo, float hi) {
    uint32_t r;  // d.hi = first operand, d.lo = second
    asm("cvt.rn.f16x2.f32 %0, %1, %2;" : "=r"(r) : "f"(hi), "f"(lo));
    return r;
}
__device__ __forceinline__ void sts32(uint32_t a, uint32_t v) {
    asm volatile("st.shared.u32 [%0], %1;" :: "r"(a), "r"(v) : "memory");
}
__device__ __forceinline__ void sts128(uint32_t a, uint32_t v0, uint32_t v1,
                                       uint32_t v2, uint32_t v3) {
    asm volatile("st.shared.v4.b32 [%0], {%1,%2,%3,%4};"
                 :: "r"(a), "r"(v0), "r"(v1), "r"(v2), "r"(v3) : "memory");
}
__device__ __forceinline__ uint32_t lds32(uint32_t a) {
    uint32_t r;
    asm("ld.shared.u32 %0, [%1];" : "=r"(r) : "r"(a));
    return r;
}
__device__ __forceinline__ uint32_t prmt(uint32_t a, uint32_t b, uint32_t c) {
    uint32_t d;
    asm("prmt.b32 %0, %1, %2, %3;" : "=r"(d) : "r"(a), "r"(b), "r"(c));
    return d;
}
__device__ __forceinline__ void mma_f16(float* d, const uint32_t* a,
                                        uint32_t b0, uint32_t b1) {
    asm volatile(
        "mma.sync.aligned.m16n8k16.row.col.f32.f16.f16.f32 "
        "{%0,%1,%2,%3}, {%4,%5,%6,%7}, {%8,%9}, {%0,%1,%2,%3};"
        : "+f"(d[0]), "+f"(d[1]), "+f"(d[2]), "+f"(d[3])
        : "r"(a[0]), "r"(a[1]), "r"(a[2]), "r"(a[3]), "r"(b0), "r"(b1));
}

// ---------------- pass 1: fragment idx pack + fp16 B fragments (probe fused) ----
// 262144 uint4 idx elements + 8192 B-fragment words. Grid 256 x 1024.
__global__ void __launch_bounds__(1024) pack_idx_kernel(
    const void* __restrict__ conv_, const float* __restrict__ zf,
    const float* __restrict__ wts)
{
    __shared__ int s_is64;
    if (threadIdx.x < 32) {
        int nz = (((const int*)conv_)[2 * threadIdx.x + 1] != 0);
        unsigned m = __ballot_sync(0xffffffffu, nz);
        if (threadIdx.x == 0) s_is64 = (m == 0) ? 1 : 0;
    }
    __syncthreads();
    const int is64 = s_is64;
    const int*       c32p = (const int*)conv_;
    const long long* c64p = (const long long*)conv_;

    int t = blockIdx.x * 1024 + threadIdx.x;   // 0 .. 262143

    // B fragments (first 8192 threads): fp16x2 {w[n][k], w[n][k+1]} (proven layout)
    if (t < 8192) {
        int q = t & 3, lane = (t >> 2) & 31, hp = (t >> 7) & 1;
        int s = (t >> 8) & 1, c = t >> 9;
        int nt = hp * 2 + (q >> 1), br = q & 1;
        int n  = nt * 8 + (lane >> 2);
        int kk = 16 * s + 2 * (lane & 3) + br * 8;
        float lo = (kk     < KL_) ? wts[n * 400 + c * KL_ + kk]     : 0.f;
        float hi = (kk + 1 < KL_) ? wts[n * 400 + c * KL_ + kk + 1] : 0.f;
        g_bfrag16[t] = f16x2_pack(lo, hi);
    }

    int lane = t & 31;
    int sg   = (t >> 5) & 1;
    int mg   = (t >> 6) & 3;
    int trow = (t >> 8) & 63;
    int c    = t >> 14;
    int base = max(0, trow - 2) * W_;
    int r  = lane >> 2, c4 = lane & 3;

    unsigned short v[8];
#pragma unroll
    for (int q = 0; q < 4; ++q) {
#pragma unroll
        for (int h = 0; h < 2; ++h) {
            int row = r + 8 * (q & 1);               // 0..15 within m-group
            int hw  = trow * 64 + mg * 16 + row;
            int k   = 16 * sg + 2 * c4 + h + 8 * (q >> 1);
            int val = 320;
            if (k < KL_) {
                int j = (c * HW_ + hw) * KL_ + k;
                if (zf[j] == 0.0f) {
                    int raw = is64 ? (int)c64p[j] : c32p[j];
                    val = (raw & 4095) - base;       // in [0, 320)
                }
            }
            v[q * 2 + h] = (unsigned short)(val << 2);
        }
    }
    ((uint4*)g_idxf)[t] = *(const uint4*)v;
}

// ---------------- SMEM layout ----------------
// windows only: 16 channels x 1312 B (328 words; words 0..319 data, 320 = 0)
#define WIN_STR  1312
#define SM_TOT   (16 * WIN_STR)    // 20992 (epilogue reuses: 17408 B needed)

// ---------------- pass 2: k-split gather -> mma.sync fp16 ----------------
// CTA = (batch pair bp, image row trow): 64 hw; 8 warps = (mg 0..3) x (sg 0..1).
// Grid 512, 3 CTAs/SM.
__global__ void __launch_bounds__(256, 3) abc_mma_kernel(
    const float* __restrict__ x,
    float* __restrict__ out)          // (B, O, H, W)
{
    extern __shared__ char sm[];
    const int tid = threadIdx.x, wid = tid >> 5, lid = tid & 31;
    const int mg = wid & 3, sg = wid >> 2;
    const int bp   = blockIdx.x >> 6;
    const int trow = blockIdx.x & 63;
    const int r0   = max(0, trow - 2);
    const int r1   = min(H_ - 1, trow + 2);
    const int nwords = (r1 - r0 + 1) * W_;        // 192..320
    const int b0   = bp * 2;

    const uint32_t win_sm = smem_u32(sm);

    // zero sentinel word (index 320) of every channel window
    if (tid < 16) sts32(win_sm + tid * WIN_STR + 1280, 0u);

    // ---- stage ALL 16 channel windows (both batches packed fp16x2) ----
    {
        const float4* pa = (const float4*)(x + (((size_t)b0 * C_) << 12) + r0 * W_);
        const float4* pb = (const float4*)(x + (((size_t)(b0 + 1) * C_) << 12) + r0 * W_);
#pragma unroll
        for (int it = 0; it < 5; ++it) {
            int i4 = tid + it * 256;              // 0..1279 over 16ch x 80 float4
            int ch = i4 / 80;
            int wg = i4 - ch * 80;
            if (wg * 4 < nwords) {
                float4 va = __ldg(pa + (ch << 10) + wg);
                float4 vb = __ldg(pb + (ch << 10) + wg);
                sts128(win_sm + ch * WIN_STR + wg * 16,
                       f16x2_pack(va.x, vb.x), f16x2_pack(va.y, vb.y),
                       f16x2_pack(va.z, vb.z), f16x2_pack(va.w, vb.w));
            }
        }
    }
    __syncthreads();   // the ONLY mainloop barrier

    // idx: uint4 e = ((c*512 + (trow*4+mg)*2 + sg)*32 + lane
    const uint4* idxp = (const uint4*)g_idxf
                      + ((size_t)((trow * 4 + mg) * 2 + sg)) * 32 + lid;
    uint4 ic = __ldg(idxp), in_;

    const uint4* Bq = (const uint4*)g_bfrag16;    // global, L1-hot

    float acc[2][4][4];
#pragma unroll
    for (int bt = 0; bt < 2; ++bt)
#pragma unroll
        for (int nt = 0; nt < 4; ++nt)
#pragma unroll
            for (int rr = 0; rr < 4; ++rr) acc[bt][nt][rr] = 0.0f;

#pragma unroll 1
    for (int c = 0; c < C_; ++c) {
        if (c + 1 < C_) in_ = __ldg(idxp + (size_t)(c + 1) * 16384);
        uint4 Bf0 = __ldg(Bq + (c * 4 + sg * 2 + 0) * 32 + lid);   // nt 0,1
        uint4 Bf1 = __ldg(Bq + (c * 4 + sg * 2 + 1) * 32 + lid);   // nt 2,3

        const uint32_t wbase = win_sm + c * WIN_STR;
        uint32_t aA[4], aB[4], w0, w1;
        w0 = lds32(wbase + (ic.x & 0xFFFF)); w1 = lds32(wbase + (ic.x >> 16));
        aA[0] = prmt(w0, w1, 0x5410u); aB[0] = prmt(w0, w1, 0x7632u);
        w0 = lds32(wbase + (ic.y & 0xFFFF)); w1 = lds32(wbase + (ic.y >> 16));
        aA[1] = prmt(w0, w1, 0x5410u); aB[1] = prmt(w0, w1, 0x7632u);
        w0 = lds32(wbase + (ic.z & 0xFFFF)); w1 = lds32(wbase + (ic.z >> 16));
        aA[2] = prmt(w0, w1, 0x5410u); aB[2] = prmt(w0, w1, 0x7632u);
        w0 = lds32(wbase + (ic.w & 0xFFFF)); w1 = lds32(wbase + (ic.w >> 16));
        aA[3] = prmt(w0, w1, 0x5410u); aB[3] = prmt(w0, w1, 0x7632u);

        mma_f16(acc[0][0], aA, Bf0.x, Bf0.y);
        mma_f16(acc[0][1], aA, Bf0.z, Bf0.w);
        mma_f16(acc[0][2], aA, Bf1.x, Bf1.y);
        mma_f16(acc[0][3], aA, Bf1.z, Bf1.w);
        mma_f16(acc[1][0], aB, Bf0.x, Bf0.y);
        mma_f16(acc[1][1], aB, Bf0.z, Bf0.w);
        mma_f16(acc[1][2], aB, Bf1.x, Bf1.y);
        mma_f16(acc[1][3], aB, Bf1.z, Bf1.w);

        ic = in_;
    }

    // ---------------- epilogue: merge s-halves in smem, then STG.128 -----------
    // ep layout: [bat][n]*68 + hwl ; bat stride 2176 words. 17408 B (reuses sm).
    __syncthreads();                 // window reads done; reuse smem
    float* ep = (float*)sm;
    if (sg == 0) {
#pragma unroll
        for (int bt = 0; bt < 2; ++bt)
#pragma unroll
            for (int nt = 0; nt < 4; ++nt)
#pragma unroll
                for (int rg = 0; rg < 4; ++rg) {
                    int n   = nt * 8 + 2 * (lid & 3) + (rg & 1);
                    int hwl = 16 * mg + (lid >> 2) + 8 * (rg >> 1);
                    ep[bt * 2176 + n * 68 + hwl] = acc[bt][nt][rg];
                }
    }
    __syncthreads();
    if (sg == 1) {
#pragma unroll
        for (int bt = 0; bt < 2; ++bt)
#pragma unroll
            for (int nt = 0; nt < 4; ++nt)
#pragma unroll
                for (int rg = 0; rg < 4; ++rg) {
                    int n   = nt * 8 + 2 * (lid & 3) + (rg & 1);
                    int hwl = 16 * mg + (lid >> 2) + 8 * (rg >> 1);
                    ep[bt * 2176 + n * 68 + hwl] += acc[bt][nt][rg];
                }
    }
    __syncthreads();
    {
        int n = tid >> 3, sub = tid & 7;
        int bat = sub >> 2, qq = sub & 3;
        const float4* src = (const float4*)(ep + bat * 2176 + n * 68 + qq * 16);
        float4* dst = (float4*)(out + (((size_t)(b0 + bat) * O_ + n) << 12)
                                + trow * 64 + qq * 16);
#pragma unroll
        for (int i = 0; i < 4; ++i) dst[i] = src[i];
    }
}

extern "C" void kernel_launch(void* const* d_in, const int* in_sizes, int n_in,
                              void* d_out, int out_size)
{
    const float* x    = (const float*)d_in[0];
    const void*  conv = d_in[1];
    const float* zf   = (const float*)d_in[2];
    const float* wts  = (const float*)d_in[3];
    float*       out  = (float*)d_out;

    pack_idx_kernel<<<256, 1024>>>(conv, zf, wts);

    cudaFuncSetAttribute(abc_mma_kernel,
                         cudaFuncAttributeMaxDynamicSharedMemorySize, SM_TOT);
    abc_mma_kernel<<<512, 256, SM_TOT>>>(x, out);
}

// round 14
// speedup vs baseline: 1.0026x; 1.0026x over previous
#include <cuda_runtime.h>
#include <cstdint>

#define C_   16
#define H_   64
#define W_   64
#define KL_  25
#define O_   32
#define HW_  4096

// Fragment-ordered idx: uint4 e = (((c*32+tile)*8+w)*2+s)*32 + lane ; 8 u16 byte
// offsets (word*4) into the tile's channel window; word in [0,384], 384 = zero
// sentinel. 4 MB.
__device__ __align__(16) unsigned short g_idxf[16 * 32 * 8 * 2 * 32 * 8];
// Pre-built fp16x2 B fragments: [c][s][hp][lane][4 u32] = 32 KB
__device__ __align__(16) uint32_t g_bfrag16[8192];

__device__ __forceinline__ uint32_t smem_u32(const void* p) {
    uint32_t a;
    asm("{ .reg .u64 t; cvta.to.shared.u64 t, %1; cvt.u32.u64 %0, t; }" : "=r"(a) : "l"(p));
    return a;
}
__device__ __forceinline__ void cpasync16(uint32_t dst, const void* src) {
    asm volatile("cp.async.ca.shared.global [%0], [%1], 16;" :: "r"(dst), "l"(src) : "memory");
}
__device__ __forceinline__ uint32_t f16x2_pack(float lo, float hi) {
    uint32_t r;  // d.hi = first operand, d.lo = second
    asm("cvt.rn.f16x2.f32 %0, %1, %2;" : "=r"(r) : "f"(hi), "f"(lo));
    return r;
}
__device__ __forceinline__ void sts32(uint32_t a, uint32_t v) {
    asm volatile("st.shared.u32 [%0], %1;" :: "r"(a), "r"(v) : "memory");
}
__device__ __forceinline__ void sts128(uint32_t a, uint32_t v0, uint32_t v1,
                                       uint32_t v2, uint32_t v3) {
    asm volatile("st.shared.v4.b32 [%0], {%1,%2,%3,%4};"
                 :: "r"(a), "r"(v0), "r"(v1), "r"(v2), "r"(v3) : "memory");
}
__device__ __forceinline__ uint32_t lds32(uint32_t a) {
    uint32_t r;
    asm("ld.shared.u32 %0, [%1];" : "=r"(r) : "r"(a));
    return r;
}
__device__ __forceinline__ uint32_t prmt(uint32_t a, uint32_t b, uint32_t c) {
    uint32_t d;
    asm("prmt.b32 %0, %1, %2, %3;" : "=r"(d) : "r"(a), "r"(b), "r"(c));
    return d;
}
__device__ __forceinline__ void mma_f16(float* d, const uint32_t* a,
                                        uint32_t b0, uint32_t b1) {
    asm volatile(
        "mma.sync.aligned.m16n8k16.row.col.f32.f16.f16.f32 "
        "{%0,%1,%2,%3}, {%4,%5,%6,%7}, {%8,%9}, {%0,%1,%2,%3};"
        : "+f"(d[0]), "+f"(d[1]), "+f"(d[2]), "+f"(d[3])
        : "r"(a[0]), "r"(a[1]), "r"(a[2]), "r"(a[3]), "r"(b0), "r"(b1));
}

// ---------------- pass 1: fragment idx pack + fp16 B fragments (probe fused) ----
// identical to R11 (proven)
__global__ void __launch_bounds__(1024) pack_idx_kernel(
    const void* __restrict__ conv_, const float* __restrict__ zf,
    const float* __restrict__ wts)
{
    __shared__ int s_is64;
    if (threadIdx.x < 32) {
        int nz = (((const int*)conv_)[2 * threadIdx.x + 1] != 0);
        unsigned m = __ballot_sync(0xffffffffu, nz);
        if (threadIdx.x == 0) s_is64 = (m == 0) ? 1 : 0;
    }
    __syncthreads();
    const int is64 = s_is64;
    const int*       c32p = (const int*)conv_;
    const long long* c64p = (const long long*)conv_;

    int t = blockIdx.x * 1024 + threadIdx.x;   // 0 .. 262143

    if (t < 8192) {
        int q = t & 3, lane = (t >> 2) & 31, hp = (t >> 7) & 1;
        int s = (t >> 8) & 1, c = t >> 9;
        int nt = hp * 2 + (q >> 1), br = q & 1;
        int n  = nt * 8 + (lane >> 2);
        int kk = 16 * s + 2 * (lane & 3) + br * 8;
        float lo = (kk     < KL_) ? wts[n * 400 + c * KL_ + kk]     : 0.f;
        float hi = (kk + 1 < KL_) ? wts[n * 400 + c * KL_ + kk + 1] : 0.f;
        g_bfrag16[t] = f16x2_pack(lo, hi);
    }

    int lane = t & 31;
    int s    = (t >> 5) & 1;
    int w    = (t >> 6) & 7;
    int tile = (t >> 9) & 31;
    int c    = t >> 14;
    int base = max(0, tile * 2 - 2) * W_;
    int r  = lane >> 2, c4 = lane & 3;

    unsigned short v[8];
#pragma unroll
    for (int q = 0; q < 4; ++q) {
#pragma unroll
        for (int h = 0; h < 2; ++h) {
            int row = r + 8 * (q & 1);
            int hw  = tile * 128 + 16 * w + row;
            int k   = 16 * s + 2 * c4 + h + ((q & 2) << 2);
            int val = 384;
            if (k < KL_) {
                int j = (c * HW_ + hw) * KL_ + k;
                if (zf[j] == 0.0f) {
                    int raw = is64 ? (int)c64p[j] : c32p[j];
                    val = (raw & 4095) - base;
                }
            }
            v[q * 2 + h] = (unsigned short)(val << 2);
        }
    }
    ((uint4*)g_idxf)[t] = *(const uint4*)v;
}

// ---------------- SMEM layout (R11) ----------------
#define SM_B     0
#define SM_WIN   32768
#define WIN_STR  1552
#define SM_TOT   (32768 + 16 * WIN_STR)    // 57600

// Issue 8 gather LDS for one idx quad into dst[0..7].
#define GATHER8(dst, wb, iv)                                            \
    do {                                                                \
        (dst)[0] = lds32((wb) + ((iv).x & 0xFFFF));                     \
        (dst)[1] = lds32((wb) + ((iv).x >> 16));                        \
        (dst)[2] = lds32((wb) + ((iv).y & 0xFFFF));                     \
        (dst)[3] = lds32((wb) + ((iv).y >> 16));                        \
        (dst)[4] = lds32((wb) + ((iv).z & 0xFFFF));                     \
        (dst)[5] = lds32((wb) + ((iv).z >> 16));                        \
        (dst)[6] = lds32((wb) + ((iv).w & 0xFFFF));                     \
        (dst)[7] = lds32((wb) + ((iv).w >> 16));                        \
    } while (0)

// ---------------- pass 2: pipelined gather -> mma.sync fp16 ----------------
// CTA = (batch pair bp, 128-hw tile): M = 128 hw, grid 256 (one wave).
__global__ void __launch_bounds__(256, 2) abc_mma_kernel(
    const float* __restrict__ x,
    float* __restrict__ out)          // (B, O, H, W)
{
    extern __shared__ char sm[];
    const int tid = threadIdx.x, wid = tid >> 5, lid = tid & 31;
    const int bp     = blockIdx.x >> 5;
    const int tile   = blockIdx.x & 31;
    const int r0     = max(0, tile * 2 - 2);
    const int r1     = min(H_ - 1, tile * 2 + 3);
    const int nwords = (r1 - r0 + 1) * W_;        // 256 or 384
    const int b0     = bp * 2;

    const uint32_t b_sm   = smem_u32(sm + SM_B);
    const uint32_t win_sm = smem_u32(sm + SM_WIN);

    // async-load fp16 B fragments (32 KB)
    {
        const char* gb = (const char*)g_bfrag16;
#pragma unroll
        for (int i = 0; i < 8; ++i)
            cpasync16(b_sm + tid * 16 + i * 4096, gb + tid * 16 + i * 4096);
        asm volatile("cp.async.commit_group;" ::: "memory");
    }
    if (tid < 16) sts32(win_sm + tid * WIN_STR + 1536, 0u);

    // ---- stage ALL 16 channel windows (both batches packed fp16x2) ----
    {
        const float4* pa = (const float4*)(x + (((size_t)b0 * C_) << 12) + r0 * W_);
        const float4* pb = (const float4*)(x + (((size_t)(b0 + 1) * C_) << 12) + r0 * W_);
#pragma unroll
        for (int it = 0; it < 6; ++it) {
            int i4 = tid + it * 256;
            int ch = i4 / 96;
            int wg = i4 - ch * 96;
            if (wg * 4 < nwords) {
                float4 va = __ldg(pa + (ch << 10) + wg);
                float4 vb = __ldg(pb + (ch << 10) + wg);
                sts128(win_sm + ch * WIN_STR + wg * 16,
                       f16x2_pack(va.x, vb.x), f16x2_pack(va.y, vb.y),
                       f16x2_pack(va.z, vb.z), f16x2_pack(va.w, vb.w));
            }
        }
    }
    asm volatile("cp.async.wait_group 0;" ::: "memory");
    __syncthreads();   // the ONLY mainloop barrier

    const uint4* idxp = (const uint4*)g_idxf + ((size_t)(tile * 8 + wid) * 2) * 32 + lid;

    float acc[2][4][4];
#pragma unroll
    for (int bt = 0; bt < 2; ++bt)
#pragma unroll
        for (int nt = 0; nt < 4; ++nt)
#pragma unroll
            for (int rr = 0; rr < 4; ++rr) acc[bt][nt][rr] = 0.0f;

    // ---- pipeline prologue: idx c0, gathers c0, idx c1 ----
    uint4 i0 = __ldg(idxp), i1 = __ldg(idxp + 32);         // idx for c=0
    uint32_t wc[16], wn[16];
    GATHER8(wc,     win_sm, i0);
    GATHER8(wc + 8, win_sm, i1);
    uint4 j0 = __ldg(idxp + 16384), j1 = __ldg(idxp + 16384 + 32);  // idx c=1

#pragma unroll 1
    for (int c = 0; c < C_; ++c) {
        // prefetch idx for channel c+2 (hide LDG latency 2 iterations deep)
        uint4 p0, p1;
        if (c + 2 < C_) {
            p0 = __ldg(idxp + (size_t)(c + 2) * 16384);
            p1 = __ldg(idxp + (size_t)(c + 2) * 16384 + 32);
        }
        // issue gathers for channel c+1 (results consumed NEXT iteration)
        if (c + 1 < C_) {
            const uint32_t wb = win_sm + (c + 1) * WIN_STR;
            GATHER8(wn,     wb, j0);
            GATHER8(wn + 8, wb, j1);
        }
        // B fragments for this channel
        const uint4* Bp = (const uint4*)(sm + SM_B) + c * 128;
        uint4 Bf0 = Bp[lid], Bf1 = Bp[32 + lid];
        uint4 Bf2 = Bp[64 + lid], Bf3 = Bp[96 + lid];

        // compute on wc (gathered last iteration)
        uint32_t aA[4], aB[4];
        {   // s = 0
            aA[0] = prmt(wc[0], wc[1], 0x5410u); aB[0] = prmt(wc[0], wc[1], 0x7632u);
            aA[1] = prmt(wc[2], wc[3], 0x5410u); aB[1] = prmt(wc[2], wc[3], 0x7632u);
            aA[2] = prmt(wc[4], wc[5], 0x5410u); aB[2] = prmt(wc[4], wc[5], 0x7632u);
            aA[3] = prmt(wc[6], wc[7], 0x5410u); aB[3] = prmt(wc[6], wc[7], 0x7632u);
            mma_f16(acc[0][0], aA, Bf0.x, Bf0.y);
            mma_f16(acc[0][1], aA, Bf0.z, Bf0.w);
            mma_f16(acc[0][2], aA, Bf1.x, Bf1.y);
            mma_f16(acc[0][3], aA, Bf1.z, Bf1.w);
            mma_f16(acc[1][0], aB, Bf0.x, Bf0.y);
            mma_f16(acc[1][1], aB, Bf0.z, Bf0.w);
            mma_f16(acc[1][2], aB, Bf1.x, Bf1.y);
            mma_f16(acc[1][3], aB, Bf1.z, Bf1.w);
        }
        {   // s = 1
            aA[0] = prmt(wc[8],  wc[9],  0x5410u); aB[0] = prmt(wc[8],  wc[9],  0x7632u);
            aA[1] = prmt(wc[10], wc[11], 0x5410u); aB[1] = prmt(wc[10], wc[11], 0x7632u);
            aA[2] = prmt(wc[12], wc[13], 0x5410u); aB[2] = prmt(wc[12], wc[13], 0x7632u);
            aA[3] = prmt(wc[14], wc[15], 0x5410u); aB[3] = prmt(wc[14], wc[15], 0x7632u);
            mma_f16(acc[0][0], aA, Bf2.x, Bf2.y);
            mma_f16(acc[0][1], aA, Bf2.z, Bf2.w);
            mma_f16(acc[0][2], aA, Bf3.x, Bf3.y);
            mma_f16(acc[0][3], aA, Bf3.z, Bf3.w);
            mma_f16(acc[1][0], aB, Bf2.x, Bf2.y);
            mma_f16(acc[1][1], aB, Bf2.z, Bf2.w);
            mma_f16(acc[1][2], aB, Bf3.x, Bf3.y);
            mma_f16(acc[1][3], aB, Bf3.z, Bf3.w);
        }
        // rotate pipeline registers
#pragma unroll
        for (int q = 0; q < 16; ++q) wc[q] = wn[q];
        j0 = p0; j1 = p1;
    }

    // ---------------- epilogue (R11-proven): regs -> SMEM -> STG.128 ----------
    __syncthreads();
    float* ep = (float*)sm;
#pragma unroll
    for (int bt = 0; bt < 2; ++bt) {
#pragma unroll
        for (int nt = 0; nt < 4; ++nt) {
#pragma unroll
            for (int rg = 0; rg < 4; ++rg) {
                int n   = nt * 8 + 2 * (lid & 3) + (rg & 1);
                int hwl = 16 * wid + (lid >> 2) + 8 * (rg >> 1);
                ep[n * 264 + bt * 132 + hwl] = acc[bt][nt][rg];
            }
        }
    }
    __syncthreads();
    {
        int n = tid >> 3, q = tid & 7;
        int bat = q >> 2, qq = q & 3;
        const float4* src = (const float4*)(ep + n * 264 + bat * 132 + qq * 32);
        float4* dst = (float4*)(out + (((size_t)(b0 + bat) * O_ + n) << 12)
                                + tile * 128 + qq * 32);
#pragma unroll
        for (int i = 0; i < 8; ++i) dst[i] = src[i];
    }
}

extern "C" void kernel_launch(void* const* d_in, const int* in_sizes, int n_in,
                              void* d_out, int out_size)
{
    const float* x    = (const float*)d_in[0];
    const void*  conv = d_in[1];
    const float* zf   = (const float*)d_in[2];
    const float* wts  = (const float*)d_in[3];
    float*       out  = (float*)d_out;

    pack_idx_kernel<<<256, 1024>>>(conv, zf, wts);

    cudaFuncSetAttribute(abc_mma_kernel,
                         cudaFuncAttributeMaxDynamicSharedMemorySize, SM_TOT);
    abc_mma_kernel<<<256, 256, SM_TOT>>>(x, out);
}

// round 15
// speedup vs baseline: 1.0860x; 1.0832x over previous
#include <cuda_runtime.h>
#include <cstdint>

#define C_   16
#define H_   64
#define W_   64
#define KL_  25
#define O_   32
#define HW_  4096

// Fragment-ordered idx: uint4 e = (((c*32+tile)*8+w)*2+s)*32 + lane ; 8 u16 byte
// offsets (word*4) into the tile's channel window; word in [0,384], 384 = zero
// sentinel. 4 MB.
__device__ __align__(16) unsigned short g_idxf[16 * 32 * 8 * 2 * 32 * 8];
// Pre-built fp16x2 B fragments: [c][s][hp][lane][4 u32] = 32 KB
__device__ __align__(16) uint32_t g_bfrag16[8192];

__device__ __forceinline__ uint32_t smem_u32(const void* p) {
    uint32_t a;
    asm("{ .reg .u64 t; cvta.to.shared.u64 t, %1; cvt.u32.u64 %0, t; }" : "=r"(a) : "l"(p));
    return a;
}
__device__ __forceinline__ void cpasync16(uint32_t dst, const void* src) {
    asm volatile("cp.async.ca.shared.global [%0], [%1], 16;" :: "r"(dst), "l"(src) : "memory");
}
__device__ __forceinline__ uint32_t f16x2_pack(float lo, float hi) {
    uint32_t r;  // d.hi = first operand, d.lo = second
    asm("cvt.rn.f16x2.f32 %0, %1, %2;" : "=r"(r) : "f"(hi), "f"(lo));
    return r;
}
__device__ __forceinline__ void sts32(uint32_t a, uint32_t v) {
    asm volatile("st.shared.u32 [%0], %1;" :: "r"(a), "r"(v) : "memory");
}
__device__ __forceinline__ void sts128(uint32_t a, uint32_t v0, uint32_t v1,
                                       uint32_t v2, uint32_t v3) {
    asm volatile("st.shared.v4.b32 [%0], {%1,%2,%3,%4};"
                 :: "r"(a), "r"(v0), "r"(v1), "r"(v2), "r"(v3) : "memory");
}
__device__ __forceinline__ uint32_t lds32(uint32_t a) {
    uint32_t r;
    asm("ld.shared.u32 %0, [%1];" : "=r"(r) : "r"(a));
    return r;
}
__device__ __forceinline__ uint32_t prmt(uint32_t a, uint32_t b, uint32_t c) {
    uint32_t d;
    asm("prmt.b32 %0, %1, %2, %3;" : "=r"(d) : "r"(a), "r"(b), "r"(c));
    return d;
}
__device__ __forceinline__ void mma_f16(float* d, const uint32_t* a,
                                        uint32_t b0, uint32_t b1) {
    asm volatile(
        "mma.sync.aligned.m16n8k16.row.col.f32.f16.f16.f32 "
        "{%0,%1,%2,%3}, {%4,%5,%6,%7}, {%8,%9}, {%0,%1,%2,%3};"
        : "+f"(d[0]), "+f"(d[1]), "+f"(d[2]), "+f"(d[3])
        : "r"(a[0]), "r"(a[1]), "r"(a[2]), "r"(a[3]), "r"(b0), "r"(b1));
}

// ---------------- pass 1: coalesced pack (block = one (c,tile) row-block) ------
// Block stages 3200 conv + 3200 zf entries coalesced into smem, then builds 512
// fragment idx elements via smem lookups. Grid 512 x 256. Blocks < 32 also build
// the fp16 B fragments (proven decode).
__global__ void __launch_bounds__(256) pack_idx_kernel(
    const void* __restrict__ conv_, const float* __restrict__ zf,
    const float* __restrict__ wts)
{
    __shared__ int   s_is64;
    __shared__ int   s_conv[3200];
    __shared__ float s_zf[3200];

    const int tid = threadIdx.x;
    const int blk = blockIdx.x;          // blk = c*32 + tile
    const int c = blk >> 5, tile = blk & 31;

    if (tid < 32) {
        int nz = (((const int*)conv_)[2 * tid + 1] != 0);
        unsigned m = __ballot_sync(0xffffffffu, nz);
        if (tid == 0) s_is64 = (m == 0) ? 1 : 0;
    }
    __syncthreads();
    const int is64 = s_is64;

    const size_t gbase = ((size_t)c * HW_ + tile * 128) * KL_;   // = blk * 3200
    if (is64) {
        const long long* cp = (const long long*)conv_ + gbase;
#pragma unroll
        for (int i = 0; i < 13; ++i) {
            int j = tid + i * 256;
            if (j < 3200) s_conv[j] = (int)cp[j];
        }
    } else {
        const int* cp = (const int*)conv_ + gbase;
#pragma unroll
        for (int i = 0; i < 13; ++i) {
            int j = tid + i * 256;
            if (j < 3200) s_conv[j] = cp[j];
        }
    }
    {
        const float* zp = zf + gbase;
#pragma unroll
        for (int i = 0; i < 13; ++i) {
            int j = tid + i * 256;
            if (j < 3200) s_zf[j] = zp[j];
        }
    }
    __syncthreads();

    const int base = max(0, tile * 2 - 2) * W_;
    const int lane = tid & 31, r = lane >> 2, c4 = lane & 3;
#pragma unroll
    for (int half = 0; half < 2; ++half) {
        int ws = (tid >> 5) + half * 8;   // 0..15 -> (w = ws>>1, s = ws&1)
        int w = ws >> 1, s = ws & 1;
        unsigned short v[8];
#pragma unroll
        for (int q = 0; q < 4; ++q) {
#pragma unroll
            for (int h = 0; h < 2; ++h) {
                int row = r + 8 * (q & 1);
                int hwl = 16 * w + row;
                int k   = 16 * s + 2 * c4 + h + ((q & 2) << 2);
                int val = 384;
                if (k < KL_) {
                    int j = hwl * KL_ + k;
                    if (s_zf[j] == 0.0f) val = (s_conv[j] & 4095) - base;
                }
                v[q * 2 + h] = (unsigned short)(val << 2);
            }
        }
        ((uint4*)g_idxf)[(size_t)(blk * 16 + ws) * 32 + lane] = *(const uint4*)v;
    }

    // B fragments (blocks 0..31, 256 words each)
    if (blk < 32) {
        int t = blk * 256 + tid;
        int q = t & 3, lane2 = (t >> 2) & 31, hp = (t >> 7) & 1;
        int s2 = (t >> 8) & 1, c2 = t >> 9;
        int nt = hp * 2 + (q >> 1), br = q & 1;
        int n  = nt * 8 + (lane2 >> 2);
        int kk = 16 * s2 + 2 * (lane2 & 3) + br * 8;
        float lo = (kk     < KL_) ? wts[n * 400 + c2 * KL_ + kk]     : 0.f;
        float hi = (kk + 1 < KL_) ? wts[n * 400 + c2 * KL_ + kk + 1] : 0.f;
        g_bfrag16[t] = f16x2_pack(lo, hi);
    }
}

// ---------------- SMEM layout (R11) ----------------
#define SM_B     0
#define SM_WIN   32768
#define WIN_STR  1552
#define SM_TOT   (32768 + 16 * WIN_STR)    // 57600

// ---------------- pass 2: gather -> mma.sync fp16 (R11 + unroll 2) -------------
__global__ void __launch_bounds__(256, 2) abc_mma_kernel(
    const float* __restrict__ x,
    float* __restrict__ out)          // (B, O, H, W)
{
    extern __shared__ char sm[];
    const int tid = threadIdx.x, wid = tid >> 5, lid = tid & 31;
    const int bp     = blockIdx.x >> 5;
    const int tile   = blockIdx.x & 31;
    const int r0     = max(0, tile * 2 - 2);
    const int r1     = min(H_ - 1, tile * 2 + 3);
    const int nwords = (r1 - r0 + 1) * W_;        // 256 or 384
    const int b0     = bp * 2;

    const uint32_t b_sm   = smem_u32(sm + SM_B);
    const uint32_t win_sm = smem_u32(sm + SM_WIN);

    // async-load fp16 B fragments (32 KB)
    {
        const char* gb = (const char*)g_bfrag16;
#pragma unroll
        for (int i = 0; i < 8; ++i)
            cpasync16(b_sm + tid * 16 + i * 4096, gb + tid * 16 + i * 4096);
        asm volatile("cp.async.commit_group;" ::: "memory");
    }
    if (tid < 16) sts32(win_sm + tid * WIN_STR + 1536, 0u);

    // ---- stage ALL 16 channel windows (both batches packed fp16x2) ----
    {
        const float4* pa = (const float4*)(x + (((size_t)b0 * C_) << 12) + r0 * W_);
        const float4* pb = (const float4*)(x + (((size_t)(b0 + 1) * C_) << 12) + r0 * W_);
#pragma unroll
        for (int it = 0; it < 6; ++it) {
            int i4 = tid + it * 256;
            int ch = i4 / 96;
            int wg = i4 - ch * 96;
            if (wg * 4 < nwords) {
                float4 va = __ldg(pa + (ch << 10) + wg);
                float4 vb = __ldg(pb + (ch << 10) + wg);
                sts128(win_sm + ch * WIN_STR + wg * 16,
                       f16x2_pack(va.x, vb.x), f16x2_pack(va.y, vb.y),
                       f16x2_pack(va.z, vb.z), f16x2_pack(va.w, vb.w));
            }
        }
    }
    asm volatile("cp.async.wait_group 0;" ::: "memory");
    __syncthreads();   // the ONLY mainloop barrier

    const uint4* idxp = (const uint4*)g_idxf + ((size_t)(tile * 8 + wid) * 2) * 32 + lid;
    uint4 ic[2], in_[2];
    ic[0] = __ldg(idxp);
    ic[1] = __ldg(idxp + 32);

    float acc[2][4][4];
#pragma unroll
    for (int bt = 0; bt < 2; ++bt)
#pragma unroll
        for (int nt = 0; nt < 4; ++nt)
#pragma unroll
            for (int rr = 0; rr < 4; ++rr) acc[bt][nt][rr] = 0.0f;

#pragma unroll 2
    for (int c = 0; c < C_; ++c) {
        if (c + 1 < C_) {
            in_[0] = __ldg(idxp + (size_t)(c + 1) * 16384);
            in_[1] = __ldg(idxp + (size_t)(c + 1) * 16384 + 32);
        }
        const uint4* Bp = (const uint4*)(sm + SM_B) + c * 128;
        uint4 Bf0 = Bp[lid], Bf1 = Bp[32 + lid];       // s=0: hp0, hp1
        uint4 Bf2 = Bp[64 + lid], Bf3 = Bp[96 + lid];  // s=1: hp0, hp1

        const uint32_t wbase = win_sm + c * WIN_STR;
        {   // s = 0
            uint4 iv = ic[0];
            uint32_t aA[4], aB[4], w0, w1;
            w0 = lds32(wbase + (iv.x & 0xFFFF)); w1 = lds32(wbase + (iv.x >> 16));
            aA[0] = prmt(w0, w1, 0x5410u); aB[0] = prmt(w0, w1, 0x7632u);
            w0 = lds32(wbase + (iv.y & 0xFFFF)); w1 = lds32(wbase + (iv.y >> 16));
            aA[1] = prmt(w0, w1, 0x5410u); aB[1] = prmt(w0, w1, 0x7632u);
            w0 = lds32(wbase + (iv.z & 0xFFFF)); w1 = lds32(wbase + (iv.z >> 16));
            aA[2] = prmt(w0, w1, 0x5410u); aB[2] = prmt(w0, w1, 0x7632u);
            w0 = lds32(wbase + (iv.w & 0xFFFF)); w1 = lds32(wbase + (iv.w >> 16));
            aA[3] = prmt(w0, w1, 0x5410u); aB[3] = prmt(w0, w1, 0x7632u);
            mma_f16(acc[0][0], aA, Bf0.x, Bf0.y);
            mma_f16(acc[0][1], aA, Bf0.z, Bf0.w);
            mma_f16(acc[0][2], aA, Bf1.x, Bf1.y);
            mma_f16(acc[0][3], aA, Bf1.z, Bf1.w);
            mma_f16(acc[1][0], aB, Bf0.x, Bf0.y);
            mma_f16(acc[1][1], aB, Bf0.z, Bf0.w);
            mma_f16(acc[1][2], aB, Bf1.x, Bf1.y);
            mma_f16(acc[1][3], aB, Bf1.z, Bf1.w);
        }
        {   // s = 1
            uint4 iv = ic[1];
            uint32_t aA[4], aB[4], w0, w1;
            w0 = lds32(wbase + (iv.x & 0xFFFF)); w1 = lds32(wbase + (iv.x >> 16));
            aA[0] = prmt(w0, w1, 0x5410u); aB[0] = prmt(w0, w1, 0x7632u);
            w0 = lds32(wbase + (iv.y & 0xFFFF)); w1 = lds32(wbase + (iv.y >> 16));
            aA[1] = prmt(w0, w1, 0x5410u); aB[1] = prmt(w0, w1, 0x7632u);
            w0 = lds32(wbase + (iv.z & 0xFFFF)); w1 = lds32(wbase + (iv.z >> 16));
            aA[2] = prmt(w0, w1, 0x5410u); aB[2] = prmt(w0, w1, 0x7632u);
            w0 = lds32(wbase + (iv.w & 0xFFFF)); w1 = lds32(wbase + (iv.w >> 16));
            aA[3] = prmt(w0, w1, 0x5410u); aB[3] = prmt(w0, w1, 0x7632u);
            mma_f16(acc[0][0], aA, Bf2.x, Bf2.y);
            mma_f16(acc[0][1], aA, Bf2.z, Bf2.w);
            mma_f16(acc[0][2], aA, Bf3.x, Bf3.y);
            mma_f16(acc[0][3], aA, Bf3.z, Bf3.w);
            mma_f16(acc[1][0], aB, Bf2.x, Bf2.y);
            mma_f16(acc[1][1], aB, Bf2.z, Bf2.w);
            mma_f16(acc[1][2], aB, Bf3.x, Bf3.y);
            mma_f16(acc[1][3], aB, Bf3.z, Bf3.w);
        }
        ic[0] = in_[0]; ic[1] = in_[1];
    }

    // ---------------- epilogue (R11-proven): regs -> SMEM -> STG.128 ----------
    __syncthreads();
    float* ep = (float*)sm;
#pragma unroll
    for (int bt = 0; bt < 2; ++bt) {
#pragma unroll
        for (int nt = 0; nt < 4; ++nt) {
#pragma unroll
            for (int rg = 0; rg < 4; ++rg) {
                int n   = nt * 8 + 2 * (lid & 3) + (rg & 1);
                int hwl = 16 * wid + (lid >> 2) + 8 * (rg >> 1);
                ep[n * 264 + bt * 132 + hwl] = acc[bt][nt][rg];
            }
        }
    }
    __syncthreads();
    {
        int n = tid >> 3, q = tid & 7;
        int bat = q >> 2, qq = q & 3;
        const float4* src = (const float4*)(ep + n * 264 + bat * 132 + qq * 32);
        float4* dst = (float4*)(out + (((size_t)(b0 + bat) * O_ + n) << 12)
                                + tile * 128 + qq * 32);
#pragma unroll
        for (int i = 0; i < 8; ++i) dst[i] = src[i];
    }
}

extern "C" void kernel_launch(void* const* d_in, const int* in_sizes, int n_in,
                              void* d_out, int out_size)
{
    const float* x    = (const float*)d_in[0];
    const void*  conv = d_in[1];
    const float* zf   = (const float*)d_in[2];
    const float* wts  = (const float*)d_in[3];
    float*       out  = (float*)d_out;

    pack_idx_kernel<<<512, 256>>>(conv, zf, wts);

    cudaFuncSetAttribute(abc_mma_kernel,
                         cudaFuncAttributeMaxDynamicSharedMemorySize, SM_TOT);
    abc_mma_kernel<<<256, 256, SM_TOT>>>(x, out);
}